// round 8
// baseline (speedup 1.0000x reference)
#include <cuda_runtime.h>

// Problem constants (fixed by the reference)
#define BB 16
#define NN 1024
#define DD 1024
#define UU 512

#define SPLITS 64
#define UCHUNK (UU / SPLITS)   // 8
#define NROWS  (BB * NN)       // 16384

#define NREAD  512             // reader blocks (32 rows each)
#define NWRITE 512             // writer blocks (32 out-rows each)
#define RBLK   32              // rows per reader block
#define RDONE  (NN / RBLK)     // reader blocks per batch = 32

// Scratch (no cudaMalloc allowed)
__device__ float    g_part[SPLITS * 2 * DD];  // partial v sums [split][2*D]
__device__ float    g_v[2 * DD];              // v_h | v_m
__device__ float    g_c[2];                   // c_h, c_m + b_out
__device__ float    g_s[2 * NROWS];           // sH | sM
__device__ unsigned g_done[BB];               // reader blocks finished / batch

// ---------------------------------------------------------------------------
// Kernel 1: partial v sums + bias constants + flag reset.
// ---------------------------------------------------------------------------
__global__ void __launch_bounds__(256) vpart(const float* __restrict__ W_h,
                                             const float* __restrict__ W_m,
                                             const float* __restrict__ w_out,
                                             const float* __restrict__ b_h,
                                             const float* __restrict__ b_m,
                                             const float* __restrict__ b_out) {
    if (blockIdx.x == 512) {
        int t = threadIdx.x;
        if (t < BB) g_done[t] = 0;             // reset flags for this launch
        float w0 = w_out[t], w1 = w_out[t + 256];
        float h = w0 * b_h[t] + w1 * b_h[t + 256];
        float m = w0 * b_m[t] + w1 * b_m[t + 256];
#pragma unroll
        for (int o = 16; o > 0; o >>= 1) {
            h += __shfl_xor_sync(0xffffffffu, h, o);
            m += __shfl_xor_sync(0xffffffffu, m, o);
        }
        __shared__ float rh[8], rm[8];
        if ((t & 31) == 0) { rh[t >> 5] = h; rm[t >> 5] = m; }
        __syncthreads();
        if (t == 0) {
            float hh = 0.f, mm = 0.f;
#pragma unroll
            for (int k = 0; k < 8; ++k) { hh += rh[k]; mm += rm[k]; }
            g_c[0] = hh;
            g_c[1] = mm + b_out[0];
        }
        return;
    }

    int gid = blockIdx.x * 256 + threadIdx.x;  // 0..131071
    int col = gid & (2 * DD - 1);              // 0..2047
    int s   = gid >> 11;                       // split 0..63
    const float* __restrict__ W = (col < DD) ? W_h : W_m;
    int d  = col & (DD - 1);
    int u0 = s * UCHUNK;
    float acc = 0.f;
#pragma unroll
    for (int k = 0; k < UCHUNK; ++k)
        acc = fmaf(w_out[u0 + k], W[(size_t)(u0 + k) * DD + d], acc);
    g_part[s * (2 * DD) + col] = acc;
}

// ---------------------------------------------------------------------------
// Kernel 2: reduce the 64 partials per column (fixed order -> deterministic).
// ---------------------------------------------------------------------------
__global__ void __launch_bounds__(256) vreduce() {
    int col = blockIdx.x * 256 + threadIdx.x;  // 0..2047
    float acc = 0.f;
#pragma unroll
    for (int s = 0; s < SPLITS; ++s)
        acc += g_part[s * (2 * DD) + col];
    g_v[col] = acc;
}

// ---------------------------------------------------------------------------
// Kernel 3 (fused streamer): blocks 0..511 are READERS, 512..1023 WRITERS.
//
// READER r: rows [r*32, r*32+32) of batch b=r/32. v_h/v_m staged in smem,
// warp-per-row dots (4 rows/warp, 8 warps). After its rows: threadfence +
// ONE atomicAdd on g_done[b]  (32 adds per counter total — no pileup).
//
// WRITER w (w-=512): out rows [w*32, w*32+32) of batch b=w/32. One thread
// acquire-polls g_done[b]==32 with nanosleep backoff, then the block streams
// 32 rows x 4KB of output (float4/thread, 16-deep store MLP per half).
//
// Readers occupy the LOW block indices -> they are all scheduled no later
// than any writer, so writer spinning can never starve a reader (deadlock-
// free). x is read with __ldcs (evict-first) so the 64MB input stream does
// not evict the L2-resident output writes.
// ---------------------------------------------------------------------------
__global__ void __launch_bounds__(256) streamer(const float* __restrict__ x,
                                                float* __restrict__ out) {
    int t = threadIdx.x;

    if (blockIdx.x < NREAD) {
        // ---------------- READER ----------------
        __shared__ float4 vsm[512];            // vh (256) | vm (256)
        ((float4*)vsm)[t]       = ((const float4*)g_v)[t];
        ((float4*)vsm)[t + 256] = ((const float4*)g_v)[t + 256];
        __syncthreads();

        int lane = t & 31;
        int warp = t >> 5;                     // 0..7
        int base = blockIdx.x * RBLK + warp * 4;
        float ch = g_c[0], cm = g_c[1];

#pragma unroll
        for (int i = 0; i < 4; ++i) {
            int row = base + i;
            const float4* __restrict__ x4 = (const float4*)(x + (size_t)row * DD);
            float ah = 0.f, am = 0.f;
#pragma unroll
            for (int k = 0; k < 8; ++k) {
                int idx = lane + 32 * k;
                float4 xv = __ldcs(&x4[idx]);
                float4 vh = vsm[idx];
                float4 vm = vsm[256 + idx];
                ah += xv.x * vh.x + xv.y * vh.y + xv.z * vh.z + xv.w * vh.w;
                am += xv.x * vm.x + xv.y * vm.y + xv.z * vm.z + xv.w * vm.w;
            }
#pragma unroll
            for (int o = 16; o > 0; o >>= 1) {
                ah += __shfl_xor_sync(0xffffffffu, ah, o);
                am += __shfl_xor_sync(0xffffffffu, am, o);
            }
            if (lane == 0) {
                g_s[row]         = ah + ch;
                g_s[NROWS + row] = am + cm;
            }
        }

        __threadfence();                       // publish g_s (all threads)
        __syncthreads();
        if (t == 0)
            atomicAdd(&g_done[blockIdx.x / RDONE], 1u);   // release via fence
    } else {
        // ---------------- WRITER ----------------
        int w  = blockIdx.x - NREAD;           // 0..511
        int b  = w >> 5;                       // batch (32 writer blocks/batch)
        int i0 = w * RBLK;                     // first global out row (b*N+i)

        if (t == 0) {
            unsigned v;
            for (;;) {
                asm volatile("ld.acquire.gpu.global.u32 %0, [%1];"
                             : "=r"(v) : "l"(&g_done[b]) : "memory");
                if (v >= RDONE) break;
                __nanosleep(128);
            }
        }
        __syncthreads();                       // all threads now see g_s[b]

        float4 m = ((const float4*)(g_s + NROWS + b * NN))[t];
        float4* __restrict__ o4 = (float4*)out;

#pragma unroll
        for (int half = 0; half < 2; ++half) {
            float sH[16];
#pragma unroll
            for (int r = 0; r < 16; ++r) sH[r] = g_s[i0 + half * 16 + r];
#pragma unroll
            for (int r = 0; r < 16; ++r) {
                float4 v = make_float4(sH[r] + m.x, sH[r] + m.y,
                                       sH[r] + m.z, sH[r] + m.w);
                o4[(size_t)(i0 + half * 16 + r) * (NN / 4) + t] = v;
            }
        }
    }
}

// ---------------------------------------------------------------------------
// Inputs (metadata order): x, W_h, b_h, W_m, b_m, w_out, b_out
// Output: float32 [B, N, N]
// ---------------------------------------------------------------------------
extern "C" void kernel_launch(void* const* d_in, const int* in_sizes, int n_in,
                              void* d_out, int out_size) {
    const float* x     = (const float*)d_in[0];
    const float* W_h   = (const float*)d_in[1];
    const float* b_h   = (const float*)d_in[2];
    const float* W_m   = (const float*)d_in[3];
    const float* b_m   = (const float*)d_in[4];
    const float* w_out = (const float*)d_in[5];
    const float* b_out = (const float*)d_in[6];
    float* out = (float*)d_out;

    vpart<<<513, 256>>>(W_h, W_m, w_out, b_h, b_m, b_out);
    vreduce<<<8, 256>>>();
    streamer<<<NREAD + NWRITE, 256>>>(x, out);
}